// round 17
// baseline (speedup 1.0000x reference)
#include <cuda_runtime.h>

#define NN 64
#define CC 960
#define CS 240
#define HW 784
#define HW4 196      // float4s per (n,c) plane
#define NC (NN*CC)   // 61440 planes
#define NBLK 47040   // scale blocks = NC*HW4/256

// Scratch (no device allocs). 16B-aligned: accessed through float4 casts.
__device__ __align__(16) float g_pooled[NC];
__device__ __align__(16) float g_hidden[NN*CS];
__device__ float g_scale[NC];

__device__ __forceinline__ float warp_sum(float s) {
    #pragma unroll
    for (int d = 16; d; d >>= 1) s += __shfl_xor_sync(0xffffffffu, s, d);
    return s;
}
__device__ __forceinline__ void pdl_trigger() {
    asm volatile("griddepcontrol.launch_dependents;");
}
__device__ __forceinline__ void pdl_wait() {
    asm volatile("griddepcontrol.wait;" ::: "memory");
}

// ---------------------------------------------------------------------------
// Kernel 1: global average pool. One warp per FOUR (n,c) planes.
// ---------------------------------------------------------------------------
__global__ void __launch_bounds__(256) pool_kernel(const float* __restrict__ x) {
    unsigned warp = (blockIdx.x * blockDim.x + threadIdx.x) >> 5;  // < NC/4
    unsigned lane = threadIdx.x & 31u;
    const float4* p = reinterpret_cast<const float4*>(x) + (size_t)warp * (4 * HW4);
    float s0 = 0.f, s1 = 0.f, s2 = 0.f, s3 = 0.f;
    #pragma unroll 3
    for (int i = lane; i < HW4; i += 32) {
        float4 a = p[i];
        float4 b = p[i + HW4];
        float4 c = p[i + 2 * HW4];
        float4 d = p[i + 3 * HW4];
        s0 += (a.x + a.y) + (a.z + a.w);
        s1 += (b.x + b.y) + (b.z + b.w);
        s2 += (c.x + c.y) + (c.z + c.w);
        s3 += (d.x + d.y) + (d.z + d.w);
    }
    s0 = warp_sum(s0); s1 = warp_sum(s1); s2 = warp_sum(s2); s3 = warp_sum(s3);
    if (lane == 0) {
        float4 r;
        r.x = s0 * (1.0f / HW); r.y = s1 * (1.0f / HW);
        r.z = s2 * (1.0f / HW); r.w = s3 * (1.0f / HW);
        reinterpret_cast<float4*>(g_pooled)[warp] = r;
    }
    pdl_trigger();
}

// ---------------------------------------------------------------------------
// Kernel 2: fc1 + relu, TILED. Grid 80 = 10 o-tiles(24) x 8 n-tiles(8).
// Block stages 8 pooled rows in smem; warp computes 3 o-rows x 8 batches
// with register accumulators -> w1 read 8x total instead of 64x per row.
// ---------------------------------------------------------------------------
__global__ void __launch_bounds__(256) fc1_kernel(
    const float* __restrict__ w1, const float* __restrict__ b1)
{
    __shared__ __align__(16) float sp[8][CC];
    const int bo = blockIdx.x >> 3;          // 0..9  -> o base = bo*24
    const int bn = blockIdx.x & 7;           // 0..7  -> n base = bn*8
    const int tid = threadIdx.x, wid = tid >> 5, lane = tid & 31;

    pdl_wait();                              // g_pooled ready
    {   // load 8 pooled rows (1920 float4s) into smem
        const float4* src = reinterpret_cast<const float4*>(g_pooled) + bn * (8 * CC / 4);
        float4* dst = reinterpret_cast<float4*>(&sp[0][0]);
        #pragma unroll
        for (int i = tid; i < 8 * CC / 4; i += 256) dst[i] = src[i];
    }
    __syncthreads();

    #pragma unroll
    for (int j = 0; j < 3; j++) {
        const int o = bo * 24 + wid * 3 + j;
        const float* wr = w1 + o * CC;
        float acc[8] = {0.f,0.f,0.f,0.f,0.f,0.f,0.f,0.f};
        for (int k = lane; k < CC; k += 32) {
            float a = __ldg(&wr[k]);
            #pragma unroll
            for (int n = 0; n < 8; n++) acc[n] += a * sp[n][k];
        }
        #pragma unroll
        for (int n = 0; n < 8; n++) {
            float s = warp_sum(acc[n]);
            if (lane == 0)
                g_hidden[(bn * 8 + n) * CS + o] = fmaxf(s + __ldg(&b1[o]), 0.f);
        }
    }
    pdl_trigger();
}

// ---------------------------------------------------------------------------
// Kernel 3: fc2 + hardsigmoid, TILED. Grid 320 = 40 c-tiles(24) x 8 n-tiles(8).
// Same scheme over k=240 (7.5 lane-iterations, predicated tail).
// ---------------------------------------------------------------------------
__global__ void __launch_bounds__(256) fc2_kernel(
    const float* __restrict__ w2, const float* __restrict__ b2)
{
    __shared__ __align__(16) float sh[8][CS];
    const int bc = blockIdx.x >> 3;          // 0..39 -> c base = bc*24
    const int bn = blockIdx.x & 7;           // 0..7  -> n base = bn*8
    const int tid = threadIdx.x, wid = tid >> 5, lane = tid & 31;

    pdl_wait();                              // g_hidden ready
    {   // load 8 hidden rows (480 float4s) into smem
        const float4* src = reinterpret_cast<const float4*>(g_hidden) + bn * (8 * CS / 4);
        float4* dst = reinterpret_cast<float4*>(&sh[0][0]);
        #pragma unroll
        for (int i = tid; i < 8 * CS / 4; i += 256) dst[i] = src[i];
    }
    __syncthreads();

    #pragma unroll
    for (int j = 0; j < 3; j++) {
        const int c = bc * 24 + wid * 3 + j;
        const float* wr = w2 + c * CS;
        float acc[8] = {0.f,0.f,0.f,0.f,0.f,0.f,0.f,0.f};
        for (int k = lane; k < CS; k += 32) {        // 7 or 8 iters per lane
            float a = __ldg(&wr[k]);
            #pragma unroll
            for (int n = 0; n < 8; n++) acc[n] += a * sh[n][k];
        }
        #pragma unroll
        for (int n = 0; n < 8; n++) {
            float s = warp_sum(acc[n]);
            if (lane == 0)
                g_scale[(bn * 8 + n) * CC + c] =
                    __saturatef((s + __ldg(&b2[c]) + 3.f) * (1.f / 6.f));
        }
    }
    pdl_trigger();
}

// ---------------------------------------------------------------------------
// Kernel 4: pure streaming scale; x load issues before the PDL wait so the
// 386MB stream overlaps the fc tail.
// ---------------------------------------------------------------------------
__global__ void __launch_bounds__(256) scale_kernel(
    const float* __restrict__ x, float* __restrict__ out)
{
    unsigned i  = blockIdx.x * 256u + threadIdx.x;          // < 12,042,240
    unsigned nc = i / HW4;
    float4 v = __ldcs(reinterpret_cast<const float4*>(x) + i);  // overlaps fc2
    pdl_wait();                                             // g_scale ready
    float sc = __ldg(&g_scale[nc]);
    v.x *= sc; v.y *= sc; v.z *= sc; v.w *= sc;
    __stcs(reinterpret_cast<float4*>(out) + i, v);
}

// ---------------------------------------------------------------------------
static void launch_pdl(const void* func, dim3 grid, dim3 block, void** args) {
    cudaLaunchConfig_t cfg = {};
    cfg.gridDim = grid; cfg.blockDim = block; cfg.stream = 0;
    cudaLaunchAttribute attr[1];
    attr[0].id = cudaLaunchAttributeProgrammaticStreamSerialization;
    attr[0].val.programmaticStreamSerializationAllowed = 1;
    cfg.attrs = attr; cfg.numAttrs = 1;
    cudaLaunchKernelExC(&cfg, func, args);
}

extern "C" void kernel_launch(void* const* d_in, const int* in_sizes, int n_in,
                              void* d_out, int out_size) {
    const float* x  = (const float*)d_in[0];
    const float* w1 = (const float*)d_in[1];
    const float* b1 = (const float*)d_in[2];
    const float* w2 = (const float*)d_in[3];
    const float* b2 = (const float*)d_in[4];
    float* out = (float*)d_out;

    pool_kernel<<<(NC / 4 * 32) / 256, 256>>>(x);           // 1920 blocks

    void* a1[] = { (void*)&w1, (void*)&b1 };
    launch_pdl((const void*)fc1_kernel, dim3(80), dim3(256), a1);

    void* a2[] = { (void*)&w2, (void*)&b2 };
    launch_pdl((const void*)fc2_kernel, dim3(320), dim3(256), a2);

    void* a3[] = { (void*)&x, (void*)&out };
    launch_pdl((const void*)scale_kernel, dim3(NBLK), dim3(256), a3);
}